// round 16
// baseline (speedup 1.0000x reference)
#include <cuda_runtime.h>
#include <cstddef>
#include <cstdint>

#define BB 4
#define TT 4096
#define DD 1024
#define NN 64
#define RR 16
#define KK 4
#define BT (BB * TT)
#define SG 32    // scan prefetch group size

// Scratch (device globals — no allocation allowed)
__device__ float g_mid[4 * 80 * BT];          // split-K partials, [kc][col][row]
__device__ float2 g_dp[BT * NN + SG * NN];    // interleaved {delta, proj}; padded tail
__device__ float g_states[BT * NN];
__device__ float g_owh[DD * NN];              // pre-split out_w hi, [c][k]
__device__ float g_owl[DD * NN];              // pre-split out_w lo

// ---------------------------------------------------------------------------
// tf32 helpers (fragment layout verified rounds 8-15)
// ---------------------------------------------------------------------------
__device__ __forceinline__ uint32_t tf32_hi(float x) {
    uint32_t r;
    asm("cvt.rna.tf32.f32 %0, %1;" : "=r"(r) : "f"(x));
    return r;
}
__device__ __forceinline__ void mma_tf32(float4& d,
                                         uint32_t a0, uint32_t a1, uint32_t a2, uint32_t a3,
                                         uint32_t b0, uint32_t b1) {
    asm("mma.sync.aligned.m16n8k8.row.col.f32.tf32.tf32.f32 "
        "{%0,%1,%2,%3}, {%4,%5,%6,%7}, {%8,%9}, {%0,%1,%2,%3};"
        : "+f"(d.x), "+f"(d.y), "+f"(d.z), "+f"(d.w)
        : "r"(a0), "r"(a1), "r"(a2), "r"(a3), "r"(b0), "r"(b1));
}
#define MMA3(ACC, AH, AL, BH, BL)                                          \
    do {                                                                   \
        mma_tf32(ACC, AL[0], AL[1], AL[2], AL[3], BH[0], BH[1]);           \
        mma_tf32(ACC, AH[0], AH[1], AH[2], AH[3], BL[0], BL[1]);           \
        mma_tf32(ACC, AH[0], AH[1], AH[2], AH[3], BH[0], BH[1]);           \
    } while (0)

__device__ __forceinline__ float fast_tanh(float v) {
    float r;
    asm("tanh.approx.f32 %0, %1;" : "=f"(r) : "f"(v));
    return r;
}

// ---------------------------------------------------------------------------
// Prep: split out_w into tf32 hi/lo once (65536 elements).
// ---------------------------------------------------------------------------
__global__ void prep_ow_kernel(const float* __restrict__ out_w)
{
    int idx = blockIdx.x * 256 + threadIdx.x;
    if (idx < DD * NN) {
        float v = out_w[idx];
        uint32_t h = tf32_hi(v);
        g_owh[idx] = __uint_as_float(h);
        g_owl[idx] = __uint_as_float(tf32_hi(v - __uint_as_float(h)));
    }
}

// ---------------------------------------------------------------------------
// Stage 1a: split-K FFMA GEMM partials (round-8 version, measured ~77us).
// 256-row x 80-col tiles, 8x10 fragments. grid (4, 64), block 256.
// ---------------------------------------------------------------------------
#define XP 264   // xs/as pitch

__global__ __launch_bounds__(256, 2) void stage1a_kernel(
    const float* __restrict__ x,
    const float* __restrict__ conv_w,
    const float* __restrict__ in_w,
    const float* __restrict__ dt_w)
{
    extern __shared__ float s1[];
    float* xs = s1;                  // 32 * 264
    float* as = s1 + 32 * XP;        // 32 * 264
    float* wb = s1 + 64 * XP;        // 32 * 80, [kk][c]
    float* scw = wb + 32 * 80;       // 32 * 4

    const int tid = threadIdx.x;
    const int koff = blockIdx.x * 256;
    const int base = blockIdx.y * 256;       // global row (b*T + t)
    const int t0 = base & (TT - 1);          // t within batch (tiles never straddle)
    const int cg = tid & 7;                  // col group (0..7)
    const int rg = tid >> 3;                 // row group (0..31)

    float acc[8][10];
#pragma unroll
    for (int i = 0; i < 8; i++)
#pragma unroll
        for (int m = 0; m < 10; m++) acc[i][m] = 0.f;

    for (int k0 = koff; k0 < koff + 256; k0 += 32) {
        // ---- load x tile (259 rows x 32 k), transposed into xs[k][row] ----
        for (int idx = tid; idx < 259 * 8; idx += 256) {
            int ri = idx >> 3, kq = idx & 7;
            int t = (ri < 256) ? (t0 + ri) : (t0 + ri - 259);  // 256..258 -> t0-3..t0-1
            float4 v = make_float4(0.f, 0.f, 0.f, 0.f);
            if (t >= 0) {
                v = *(const float4*)(x + (size_t)(base - t0 + t) * DD + k0 + 4 * kq);
            }
            int kk = 4 * kq;
            xs[(kk + 0) * XP + ri] = v.x;
            xs[(kk + 1) * XP + ri] = v.y;
            xs[(kk + 2) * XP + ri] = v.z;
            xs[(kk + 3) * XP + ri] = v.w;
        }
        // ---- load weights: wb[kk][c] ----
        for (int idx = tid; idx < 80 * 32; idx += 256) {
            int c = idx >> 5, kk = idx & 31;
            float w = (c < 64) ? in_w[(size_t)c * DD + k0 + kk]
                               : dt_w[(size_t)(c - 64) * DD + k0 + kk];
            wb[kk * 80 + c] = w;
        }
        // ---- load conv_w chunk ----
        if (tid < 128) {
            int kk = tid >> 2, j = tid & 3;
            scw[kk * 4 + j] = conv_w[(size_t)(k0 + kk) * KK + j];
        }
        __syncthreads();

        // ---- build conv A-tile ----
        for (int idx = tid; idx < 32 * 256; idx += 256) {
            int kk = idx >> 8, r = idx & 255;
            const float* xr = xs + kk * XP;
            float c0 = scw[kk * 4 + 0], c1 = scw[kk * 4 + 1];
            float c2 = scw[kk * 4 + 2], c3 = scw[kk * 4 + 3];
            int rm1 = r - 1; if (rm1 < 0) rm1 += 259;
            int rm2 = r - 2; if (rm2 < 0) rm2 += 259;
            int rm3 = r - 3; if (rm3 < 0) rm3 += 259;
            float v = xr[r];
            v = fmaf(c3, xr[r], v);
            v = fmaf(c2, xr[rm1], v);
            v = fmaf(c1, xr[rm2], v);
            v = fmaf(c0, xr[rm3], v);
            as[kk * XP + r] = v;
        }
        __syncthreads();

        // ---- FFMA main loop: 8 rows x (8 conv-cols + 2 dt-cols) ----
#pragma unroll 4
        for (int kk = 0; kk < 32; kk++) {
            float4 av0 = *(float4*)(as + kk * XP + 8 * rg);
            float4 av1 = *(float4*)(as + kk * XP + 8 * rg + 4);
            float4 xv0 = *(float4*)(xs + kk * XP + 8 * rg);
            float4 xv1 = *(float4*)(xs + kk * XP + 8 * rg + 4);
            float a[8] = {av0.x, av0.y, av0.z, av0.w, av1.x, av1.y, av1.z, av1.w};
            float xw[8] = {xv0.x, xv0.y, xv0.z, xv0.w, xv1.x, xv1.y, xv1.z, xv1.w};
            const float* wk = wb + kk * 80;
            float b[8];
#pragma unroll
            for (int m = 0; m < 8; m++) b[m] = wk[cg + 8 * m];
            float bd0 = wk[64 + cg];
            float bd1 = wk[72 + cg];
#pragma unroll
            for (int i = 0; i < 8; i++) {
#pragma unroll
                for (int m = 0; m < 8; m++)
                    acc[i][m] = fmaf(a[i], b[m], acc[i][m]);
                acc[i][8] = fmaf(xw[i], bd0, acc[i][8]);
                acc[i][9] = fmaf(xw[i], bd1, acc[i][9]);
            }
        }
        __syncthreads();
    }

    // ---- write partials, column-major g_mid[kc][c][row], float4 stores ----
    {
        float* mid = g_mid + (size_t)blockIdx.x * 80 * BT;
        size_t row0 = base + 8 * rg;
#pragma unroll
        for (int m = 0; m < 10; m++) {
            int c = (m < 8) ? (cg + 8 * m) : (64 + 8 * (m - 8) + cg);
            float* dst = mid + (size_t)c * BT + row0;
            *(float4*)(dst)     = make_float4(acc[0][m], acc[1][m], acc[2][m], acc[3][m]);
            *(float4*)(dst + 4) = make_float4(acc[4][m], acc[5][m], acc[6][m], acc[7][m]);
        }
    }
}

// ---------------------------------------------------------------------------
// Stage 1b: reduce partials, biases, tanh, tr_w GEMM; write interleaved g_dp.
// EXACT round-8/13/14 version (measured 19.8us). g_mid is [kc][c][row].
// ---------------------------------------------------------------------------
__global__ __launch_bounds__(256) void stage1b_kernel(
    const float* __restrict__ in_b,
    const float* __restrict__ dt_b,
    const float* __restrict__ tr_w)
{
    __shared__ float sdm[64 * 16];
    __shared__ float str[16 * 64];
    __shared__ float sproj[64 * 68];   // [r][c], pitch 68

    const int tid = threadIdx.x;
    const int base = blockIdx.x * 64;
    const int cg = tid & 15;
    const int rg = tid >> 4;

    for (int idx = tid; idx < NN * RR; idx += 256) {
        int n = idx >> 4, r = idx & 15;
        str[r * 64 + n] = tr_w[idx];
    }

    float dtb = dt_b[cg];
#pragma unroll
    for (int i = 0; i < 4; i++) {
        size_t row = base + 4 * rg + i;
#pragma unroll
        for (int m = 0; m < 4; m++) {
            int c = cg + 16 * m;
            float v = in_b[c];
#pragma unroll
            for (int kc = 0; kc < 4; kc++)
                v += g_mid[((size_t)kc * 80 + c) * BT + row];
            sproj[(4 * rg + i) * 68 + c] = v;
        }
        float dm = dtb;
#pragma unroll
        for (int kc = 0; kc < 4; kc++)
            dm += g_mid[((size_t)kc * 80 + 64 + cg) * BT + row];
        sdm[(4 * rg + i) * 16 + cg] = tanhf(dm);
    }
    __syncthreads();

    float a2[4][4];
#pragma unroll
    for (int i = 0; i < 4; i++)
#pragma unroll
        for (int j = 0; j < 4; j++) a2[i][j] = 0.f;
#pragma unroll
    for (int r = 0; r < 16; r++) {
        float d0 = sdm[(4 * rg + 0) * 16 + r];
        float d1 = sdm[(4 * rg + 1) * 16 + r];
        float d2 = sdm[(4 * rg + 2) * 16 + r];
        float d3 = sdm[(4 * rg + 3) * 16 + r];
        float w0 = str[r * 64 + 4 * cg + 0];
        float w1 = str[r * 64 + 4 * cg + 1];
        float w2 = str[r * 64 + 4 * cg + 2];
        float w3 = str[r * 64 + 4 * cg + 3];
        a2[0][0] = fmaf(d0, w0, a2[0][0]); a2[0][1] = fmaf(d0, w1, a2[0][1]);
        a2[0][2] = fmaf(d0, w2, a2[0][2]); a2[0][3] = fmaf(d0, w3, a2[0][3]);
        a2[1][0] = fmaf(d1, w0, a2[1][0]); a2[1][1] = fmaf(d1, w1, a2[1][1]);
        a2[1][2] = fmaf(d1, w2, a2[1][2]); a2[1][3] = fmaf(d1, w3, a2[1][3]);
        a2[2][0] = fmaf(d2, w0, a2[2][0]); a2[2][1] = fmaf(d2, w1, a2[2][1]);
        a2[2][2] = fmaf(d2, w2, a2[2][2]); a2[2][3] = fmaf(d2, w3, a2[2][3]);
        a2[3][0] = fmaf(d3, w0, a2[3][0]); a2[3][1] = fmaf(d3, w1, a2[3][1]);
        a2[3][2] = fmaf(d3, w2, a2[3][2]); a2[3][3] = fmaf(d3, w3, a2[3][3]);
    }
#pragma unroll
    for (int i = 0; i < 4; i++) {
        size_t row = base + 4 * rg + i;
        const float* pr = sproj + (4 * rg + i) * 68 + 4 * cg;
        float4 v0 = make_float4(a2[i][0], pr[0], a2[i][1], pr[1]);
        float4 v1 = make_float4(a2[i][2], pr[2], a2[i][3], pr[3]);
        float* dst = (float*)(g_dp + row * NN + 4 * cg);
        *(float4*)(dst) = v0;
        *(float4*)(dst + 4) = v1;
    }
}

// ---------------------------------------------------------------------------
// Stage 2: sequential scan — round-8/13 form (measured best, ~104us).
// silu(y) = h*(1 + tanh(h)), h = y/2  =>  s' = fmaf(h, tanh(h), h + p)
// 8 blocks x 32 threads, SG=32 double buffer of float2 {d/2, p}.
// ---------------------------------------------------------------------------
__global__ __launch_bounds__(32) void scan_kernel()
{
    const int chain = blockIdx.x * 32 + threadIdx.x;   // 8 blocks x 32 threads
    const int b = chain >> 6;
    const int n = chain & 63;
    const float2* pdp = g_dp + (size_t)b * TT * NN + n;
    float* ps = g_states + (size_t)b * TT * NN + n;

    float s = 0.f;

    float2 dpA[SG];   // .x = d/2, .y = p
#pragma unroll
    for (int i = 0; i < SG; i++) {
        float2 v = pdp[i * NN];
        dpA[i] = make_float2(0.5f * v.x, v.y);
    }

    for (int t0 = 0; t0 < TT; t0 += SG) {
        float2 dpB[SG];
        int tn = t0 + SG;
        // padded tail: reads past TT land in the pad region, values unused
#pragma unroll
        for (int i = 0; i < SG; i++) dpB[i] = pdp[(tn + i) * NN];
#pragma unroll
        for (int i = 0; i < SG; i++) {
            float hd = dpA[i].x, p = dpA[i].y;
            float h = fmaf(s, 0.5f, hd);     // chain +4
            float th = fast_tanh(h);         // +~40 (measured MUFU dep latency)
            float hp = h + p;                // off-chain
            s = fmaf(h, th, hp);             // +4
            ps[(t0 + i) * NN] = s;
        }
#pragma unroll
        for (int i = 0; i < SG; i++) {
            dpA[i] = make_float2(0.5f * dpB[i].x, dpB[i].y);
        }
    }
}

// ---------------------------------------------------------------------------
// Stage 3: out = states @ out_w^T + out_b via split-tf32 mma.sync (v2:
// A split once cooperatively into smem, B pre-split by prep). ~35us measured.
// Block 128x64, 8 warps, K=64.
// ---------------------------------------------------------------------------
#define S3PAD 68

__global__ __launch_bounds__(256) void stage3_kernel(
    const float* __restrict__ out_b,
    float* __restrict__ out)
{
    extern __shared__ float smem3[];
    float* sAh = smem3;                   // [128][S3PAD]
    float* sAl = sAh + 128 * S3PAD;       // [128][S3PAD]
    float* sBh = sAl + 128 * S3PAD;       // [64][S3PAD]
    float* sBl = sBh + 64 * S3PAD;        // [64][S3PAD]

    const int tid = threadIdx.x;
    const int rbase = blockIdx.y * 128;
    const int cbase = blockIdx.x * 64;
    const int warp = tid >> 5;
    const int lane = tid & 31;
    const int wm = warp >> 1;
    const int wn = warp & 1;
    const int g = lane >> 2;
    const int tg = lane & 3;

    for (int idx = tid; idx < 128 * 16; idx += 256) {
        int r = idx >> 4, q = idx & 15;
        float4 v = *(const float4*)(g_states + (size_t)(rbase + r) * NN + 4 * q);
        float vv[4] = {v.x, v.y, v.z, v.w};
        float hh[4], ll[4];
#pragma unroll
        for (int j = 0; j < 4; j++) {
            uint32_t h = tf32_hi(vv[j]);
            hh[j] = __uint_as_float(h);
            ll[j] = __uint_as_float(tf32_hi(vv[j] - __uint_as_float(h)));
        }
        *(float4*)(sAh + r * S3PAD + 4 * q) = make_float4(hh[0], hh[1], hh[2], hh[3]);
        *(float4*)(sAl + r * S3PAD + 4 * q) = make_float4(ll[0], ll[1], ll[2], ll[3]);
    }
    for (int idx = tid; idx < 64 * 16; idx += 256) {
        int c = idx >> 4, q = idx & 15;
        *(float4*)(sBh + c * S3PAD + 4 * q) =
            *(const float4*)(g_owh + (size_t)(cbase + c) * NN + 4 * q);
        *(float4*)(sBl + c * S3PAD + 4 * q) =
            *(const float4*)(g_owl + (size_t)(cbase + c) * NN + 4 * q);
    }
    __syncthreads();

    float4 acc[2][4];
#pragma unroll
    for (int i = 0; i < 2; i++)
#pragma unroll
        for (int j = 0; j < 4; j++) acc[i][j] = make_float4(0.f, 0.f, 0.f, 0.f);

#pragma unroll
    for (int k0 = 0; k0 < 64; k0 += 8) {
        uint32_t ahi[2][4], alo[2][4];
#pragma unroll
        for (int mf = 0; mf < 2; mf++) {
            int r0 = wm * 32 + mf * 16 + g;
            ahi[mf][0] = __float_as_uint(sAh[r0 * S3PAD + k0 + tg]);
            ahi[mf][1] = __float_as_uint(sAh[(r0 + 8) * S3PAD + k0 + tg]);
            ahi[mf][2] = __float_as_uint(sAh[r0 * S3PAD + k0 + tg + 4]);
            ahi[mf][3] = __float_as_uint(sAh[(r0 + 8) * S3PAD + k0 + tg + 4]);
            alo[mf][0] = __float_as_uint(sAl[r0 * S3PAD + k0 + tg]);
            alo[mf][1] = __float_as_uint(sAl[(r0 + 8) * S3PAD + k0 + tg]);
            alo[mf][2] = __float_as_uint(sAl[r0 * S3PAD + k0 + tg + 4]);
            alo[mf][3] = __float_as_uint(sAl[(r0 + 8) * S3PAD + k0 + tg + 4]);
        }
        uint32_t bhi[4][2], blo[4][2];
#pragma unroll
        for (int nf = 0; nf < 4; nf++) {
            int c0 = wn * 32 + nf * 8 + g;
            bhi[nf][0] = __float_as_uint(sBh[c0 * S3PAD + k0 + tg]);
            bhi[nf][1] = __float_as_uint(sBh[c0 * S3PAD + k0 + tg + 4]);
            blo[nf][0] = __float_as_uint(sBl[c0 * S3PAD + k0 + tg]);
            blo[nf][1] = __float_as_uint(sBl[c0 * S3PAD + k0 + tg + 4]);
        }
#pragma unroll
        for (int mf = 0; mf < 2; mf++) {
#pragma unroll
            for (int nf = 0; nf < 4; nf++) {
                MMA3(acc[mf][nf], ahi[mf], alo[mf], bhi[nf], blo[nf]);
            }
        }
    }

#pragma unroll
    for (int nf = 0; nf < 4; nf++) {
        int c = cbase + wn * 32 + nf * 8 + 2 * tg;
        float b0 = out_b[c], b1 = out_b[c + 1];
#pragma unroll
        for (int mf = 0; mf < 2; mf++) {
            int r0 = rbase + wm * 32 + mf * 16 + g;
            float4 v = acc[mf][nf];
            *(float2*)(out + (size_t)r0 * DD + c) = make_float2(v.x + b0, v.y + b1);
            *(float2*)(out + (size_t)(r0 + 8) * DD + c) = make_float2(v.z + b0, v.w + b1);
        }
    }
}

// ---------------------------------------------------------------------------
extern "C" void kernel_launch(void* const* d_in, const int* in_sizes, int n_in,
                              void* d_out, int out_size)
{
    const float* x      = (const float*)d_in[0];
    const float* conv_w = (const float*)d_in[1];
    const float* in_w   = (const float*)d_in[2];
    const float* in_b   = (const float*)d_in[3];
    const float* dt_w   = (const float*)d_in[4];
    const float* dt_b   = (const float*)d_in[5];
    const float* tr_w   = (const float*)d_in[6];
    const float* out_w  = (const float*)d_in[7];
    const float* out_b  = (const float*)d_in[8];
    float* out = (float*)d_out;

    const int s1_smem = (64 * XP + 32 * 80 + 32 * 4) * sizeof(float);  // 78336 B
    cudaFuncSetAttribute(stage1a_kernel,
                         cudaFuncAttributeMaxDynamicSharedMemorySize, s1_smem);
    const int s3_smem = (2 * 128 + 2 * 64) * S3PAD * sizeof(float);    // 104448 B
    cudaFuncSetAttribute(stage3_kernel,
                         cudaFuncAttributeMaxDynamicSharedMemorySize, s3_smem);

    prep_ow_kernel<<<256, 256>>>(out_w);
    stage1a_kernel<<<dim3(4, 64), 256, s1_smem>>>(x, conv_w, in_w, dt_w);
    stage1b_kernel<<<256, 256>>>(in_b, dt_b, tr_w);
    scan_kernel<<<8, 32>>>();
    stage3_kernel<<<dim3(16, 128), 256, s3_smem>>>(out_b, out);
}

// round 17
// speedup vs baseline: 1.0600x; 1.0600x over previous
#include <cuda_runtime.h>
#include <cstddef>
#include <cstdint>

#define BB 4
#define TT 4096
#define DD 1024
#define NN 64
#define RR 16
#define KK 4
#define BT (BB * TT)
#define SG 32    // scan prefetch group size

// Scratch (device globals — no allocation allowed)
__device__ float g_mid[4 * BT * 80];          // split-K partials, [kc][row][80]
__device__ float2 g_dp[BT * NN + SG * NN];    // interleaved {delta, proj}; padded tail
__device__ float g_states[BT * NN];
__device__ float g_owh[DD * NN];              // pre-split out_w hi, [c][k]
__device__ float g_owl[DD * NN];              // pre-split out_w lo

// ---------------------------------------------------------------------------
// tf32 helpers (fragment layout verified rounds 8-16)
// ---------------------------------------------------------------------------
__device__ __forceinline__ uint32_t tf32_hi(float x) {
    uint32_t r;
    asm("cvt.rna.tf32.f32 %0, %1;" : "=r"(r) : "f"(x));
    return r;
}
__device__ __forceinline__ void mma_tf32(float4& d,
                                         uint32_t a0, uint32_t a1, uint32_t a2, uint32_t a3,
                                         uint32_t b0, uint32_t b1) {
    asm("mma.sync.aligned.m16n8k8.row.col.f32.tf32.tf32.f32 "
        "{%0,%1,%2,%3}, {%4,%5,%6,%7}, {%8,%9}, {%0,%1,%2,%3};"
        : "+f"(d.x), "+f"(d.y), "+f"(d.z), "+f"(d.w)
        : "r"(a0), "r"(a1), "r"(a2), "r"(a3), "r"(b0), "r"(b1));
}
#define MMA3(ACC, AH, AL, BH, BL)                                          \
    do {                                                                   \
        mma_tf32(ACC, AL[0], AL[1], AL[2], AL[3], BH[0], BH[1]);           \
        mma_tf32(ACC, AH[0], AH[1], AH[2], AH[3], BL[0], BL[1]);           \
        mma_tf32(ACC, AH[0], AH[1], AH[2], AH[3], BH[0], BH[1]);           \
    } while (0)

__device__ __forceinline__ float fast_tanh(float v) {
    float r;
    asm("tanh.approx.f32 %0, %1;" : "=f"(r) : "f"(v));
    return r;
}

// ---------------------------------------------------------------------------
// Prep: split out_w into tf32 hi/lo once (65536 elements).
// ---------------------------------------------------------------------------
__global__ void prep_ow_kernel(const float* __restrict__ out_w)
{
    int idx = blockIdx.x * 256 + threadIdx.x;
    if (idx < DD * NN) {
        float v = out_w[idx];
        uint32_t h = tf32_hi(v);
        g_owh[idx] = __uint_as_float(h);
        g_owl[idx] = __uint_as_float(tf32_hi(v - __uint_as_float(h)));
    }
}

// ---------------------------------------------------------------------------
// Stage 1a: split-K FFMA GEMM partials — EXACT round-8 version (~73us):
// 256-row x 80-col tiles, 8x10 fragments, grid (4, 64), block 256.
// Writes g_mid [kc][row][80] row-major (coalesced scalar stores).
// ---------------------------------------------------------------------------
#define XP 264   // xs/as pitch

__global__ __launch_bounds__(256, 2) void stage1a_kernel(
    const float* __restrict__ x,
    const float* __restrict__ conv_w,
    const float* __restrict__ in_w,
    const float* __restrict__ dt_w)
{
    extern __shared__ float s1[];
    float* xs = s1;                  // 32 * 264
    float* as = s1 + 32 * XP;        // 32 * 264
    float* wb = s1 + 64 * XP;        // 32 * 80, [kk][c]
    float* scw = wb + 32 * 80;       // 32 * 4

    const int tid = threadIdx.x;
    const int koff = blockIdx.x * 256;
    const int base = blockIdx.y * 256;       // global row (b*T + t)
    const int t0 = base & (TT - 1);          // t within batch (tiles never straddle)
    const int cg = tid & 7;                  // col group (0..7)
    const int rg = tid >> 3;                 // row group (0..31)

    float acc[8][10];
#pragma unroll
    for (int i = 0; i < 8; i++)
#pragma unroll
        for (int m = 0; m < 10; m++) acc[i][m] = 0.f;

    for (int k0 = koff; k0 < koff + 256; k0 += 32) {
        // ---- load x tile (259 rows x 32 k), transposed into xs[k][row] ----
        for (int idx = tid; idx < 259 * 8; idx += 256) {
            int ri = idx >> 3, kq = idx & 7;
            int t = (ri < 256) ? (t0 + ri) : (t0 + ri - 259);  // 256..258 -> t0-3..t0-1
            float4 v = make_float4(0.f, 0.f, 0.f, 0.f);
            if (t >= 0) {
                v = *(const float4*)(x + (size_t)(base - t0 + t) * DD + k0 + 4 * kq);
            }
            int kk = 4 * kq;
            xs[(kk + 0) * XP + ri] = v.x;
            xs[(kk + 1) * XP + ri] = v.y;
            xs[(kk + 2) * XP + ri] = v.z;
            xs[(kk + 3) * XP + ri] = v.w;
        }
        // ---- load weights: wb[kk][c] ----
        for (int idx = tid; idx < 80 * 32; idx += 256) {
            int c = idx >> 5, kk = idx & 31;
            float w = (c < 64) ? in_w[(size_t)c * DD + k0 + kk]
                               : dt_w[(size_t)(c - 64) * DD + k0 + kk];
            wb[kk * 80 + c] = w;
        }
        // ---- load conv_w chunk ----
        if (tid < 128) {
            int kk = tid >> 2, j = tid & 3;
            scw[kk * 4 + j] = conv_w[(size_t)(k0 + kk) * KK + j];
        }
        __syncthreads();

        // ---- build conv A-tile ----
        for (int idx = tid; idx < 32 * 256; idx += 256) {
            int kk = idx >> 8, r = idx & 255;
            const float* xr = xs + kk * XP;
            float c0 = scw[kk * 4 + 0], c1 = scw[kk * 4 + 1];
            float c2 = scw[kk * 4 + 2], c3 = scw[kk * 4 + 3];
            int rm1 = r - 1; if (rm1 < 0) rm1 += 259;
            int rm2 = r - 2; if (rm2 < 0) rm2 += 259;
            int rm3 = r - 3; if (rm3 < 0) rm3 += 259;
            float v = xr[r];
            v = fmaf(c3, xr[r], v);
            v = fmaf(c2, xr[rm1], v);
            v = fmaf(c1, xr[rm2], v);
            v = fmaf(c0, xr[rm3], v);
            as[kk * XP + r] = v;
        }
        __syncthreads();

        // ---- FFMA main loop: 8 rows x (8 conv-cols + 2 dt-cols) ----
#pragma unroll 4
        for (int kk = 0; kk < 32; kk++) {
            float4 av0 = *(float4*)(as + kk * XP + 8 * rg);
            float4 av1 = *(float4*)(as + kk * XP + 8 * rg + 4);
            float4 xv0 = *(float4*)(xs + kk * XP + 8 * rg);
            float4 xv1 = *(float4*)(xs + kk * XP + 8 * rg + 4);
            float a[8] = {av0.x, av0.y, av0.z, av0.w, av1.x, av1.y, av1.z, av1.w};
            float xw[8] = {xv0.x, xv0.y, xv0.z, xv0.w, xv1.x, xv1.y, xv1.z, xv1.w};
            const float* wk = wb + kk * 80;
            float b[8];
#pragma unroll
            for (int m = 0; m < 8; m++) b[m] = wk[cg + 8 * m];
            float bd0 = wk[64 + cg];
            float bd1 = wk[72 + cg];
#pragma unroll
            for (int i = 0; i < 8; i++) {
#pragma unroll
                for (int m = 0; m < 8; m++)
                    acc[i][m] = fmaf(a[i], b[m], acc[i][m]);
                acc[i][8] = fmaf(xw[i], bd0, acc[i][8]);
                acc[i][9] = fmaf(xw[i], bd1, acc[i][9]);
            }
        }
        __syncthreads();
    }

    // ---- write partials, row-major g_mid[kc][row][80] (coalesced) ----
    {
        float* mid = g_mid + (size_t)blockIdx.x * BT * 80;
#pragma unroll
        for (int i = 0; i < 8; i++) {
            size_t row = base + 8 * rg + i;
#pragma unroll
            for (int m = 0; m < 8; m++) {
                mid[row * 80 + cg + 8 * m] = acc[i][m];
            }
            mid[row * 80 + 64 + cg] = acc[i][8];
            mid[row * 80 + 72 + cg] = acc[i][9];
        }
    }
}

// ---------------------------------------------------------------------------
// Stage 1b: reduce partials, biases, tanh, tr_w GEMM; write interleaved g_dp.
// EXACT round-8 version (g_mid [kc][row][80], coalesced reads). ~19.8us.
// ---------------------------------------------------------------------------
__global__ __launch_bounds__(256) void stage1b_kernel(
    const float* __restrict__ in_b,
    const float* __restrict__ dt_b,
    const float* __restrict__ tr_w)
{
    __shared__ float sdm[64 * 16];
    __shared__ float str[16 * 64];
    __shared__ float sproj[64 * 68];   // [r][c], pitch 68

    const int tid = threadIdx.x;
    const int base = blockIdx.x * 64;
    const int cg = tid & 15;
    const int rg = tid >> 4;

    for (int idx = tid; idx < NN * RR; idx += 256) {
        int n = idx >> 4, r = idx & 15;
        str[r * 64 + n] = tr_w[idx];
    }

    float dtb = dt_b[cg];
#pragma unroll
    for (int i = 0; i < 4; i++) {
        size_t row = base + 4 * rg + i;
#pragma unroll
        for (int m = 0; m < 4; m++) {
            int c = cg + 16 * m;
            float v = in_b[c];
#pragma unroll
            for (int kc = 0; kc < 4; kc++)
                v += g_mid[((size_t)kc * BT + row) * 80 + c];
            sproj[(4 * rg + i) * 68 + c] = v;
        }
        float dm = dtb;
#pragma unroll
        for (int kc = 0; kc < 4; kc++)
            dm += g_mid[((size_t)kc * BT + row) * 80 + 64 + cg];
        sdm[(4 * rg + i) * 16 + cg] = tanhf(dm);
    }
    __syncthreads();

    float a2[4][4];
#pragma unroll
    for (int i = 0; i < 4; i++)
#pragma unroll
        for (int j = 0; j < 4; j++) a2[i][j] = 0.f;
#pragma unroll
    for (int r = 0; r < 16; r++) {
        float d0 = sdm[(4 * rg + 0) * 16 + r];
        float d1 = sdm[(4 * rg + 1) * 16 + r];
        float d2 = sdm[(4 * rg + 2) * 16 + r];
        float d3 = sdm[(4 * rg + 3) * 16 + r];
        float w0 = str[r * 64 + 4 * cg + 0];
        float w1 = str[r * 64 + 4 * cg + 1];
        float w2 = str[r * 64 + 4 * cg + 2];
        float w3 = str[r * 64 + 4 * cg + 3];
        a2[0][0] = fmaf(d0, w0, a2[0][0]); a2[0][1] = fmaf(d0, w1, a2[0][1]);
        a2[0][2] = fmaf(d0, w2, a2[0][2]); a2[0][3] = fmaf(d0, w3, a2[0][3]);
        a2[1][0] = fmaf(d1, w0, a2[1][0]); a2[1][1] = fmaf(d1, w1, a2[1][1]);
        a2[1][2] = fmaf(d1, w2, a2[1][2]); a2[1][3] = fmaf(d1, w3, a2[1][3]);
        a2[2][0] = fmaf(d2, w0, a2[2][0]); a2[2][1] = fmaf(d2, w1, a2[2][1]);
        a2[2][2] = fmaf(d2, w2, a2[2][2]); a2[2][3] = fmaf(d2, w3, a2[2][3]);
        a2[3][0] = fmaf(d3, w0, a2[3][0]); a2[3][1] = fmaf(d3, w1, a2[3][1]);
        a2[3][2] = fmaf(d3, w2, a2[3][2]); a2[3][3] = fmaf(d3, w3, a2[3][3]);
    }
    // ---- write interleaved {delta, proj} ----
#pragma unroll
    for (int i = 0; i < 4; i++) {
        size_t row = base + 4 * rg + i;
        const float* pr = sproj + (4 * rg + i) * 68 + 4 * cg;
        float4 v0 = make_float4(a2[i][0], pr[0], a2[i][1], pr[1]);
        float4 v1 = make_float4(a2[i][2], pr[2], a2[i][3], pr[3]);
        float* dst = (float*)(g_dp + row * NN + 4 * cg);
        *(float4*)(dst) = v0;
        *(float4*)(dst + 4) = v1;
    }
}

// ---------------------------------------------------------------------------
// Stage 2: sequential scan — measured-best form (~104us, at MUFU-latency floor).
// silu(y) = h*(1 + tanh(h)), h = y/2  =>  s' = fmaf(h, tanh(h), h + p)
// 8 blocks x 32 threads, SG=32 double buffer of float2 {d/2, p}.
// ---------------------------------------------------------------------------
__global__ __launch_bounds__(32) void scan_kernel()
{
    const int chain = blockIdx.x * 32 + threadIdx.x;   // 8 blocks x 32 threads
    const int b = chain >> 6;
    const int n = chain & 63;
    const float2* pdp = g_dp + (size_t)b * TT * NN + n;
    float* ps = g_states + (size_t)b * TT * NN + n;

    float s = 0.f;

    float2 dpA[SG];   // .x = d/2, .y = p
#pragma unroll
    for (int i = 0; i < SG; i++) {
        float2 v = pdp[i * NN];
        dpA[i] = make_float2(0.5f * v.x, v.y);
    }

    for (int t0 = 0; t0 < TT; t0 += SG) {
        float2 dpB[SG];
        int tn = t0 + SG;
        // padded tail: reads past TT land in the pad region, values unused
#pragma unroll
        for (int i = 0; i < SG; i++) dpB[i] = pdp[(tn + i) * NN];
#pragma unroll
        for (int i = 0; i < SG; i++) {
            float hd = dpA[i].x, p = dpA[i].y;
            float h = fmaf(s, 0.5f, hd);     // chain +4
            float th = fast_tanh(h);         // +~40 (measured MUFU dep latency)
            float hp = h + p;                // off-chain
            s = fmaf(h, th, hp);             // +4
            ps[(t0 + i) * NN] = s;
        }
#pragma unroll
        for (int i = 0; i < SG; i++) {
            dpA[i] = make_float2(0.5f * dpB[i].x, dpB[i].y);
        }
    }
}

// ---------------------------------------------------------------------------
// Stage 3: out = states @ out_w^T + out_b via split-tf32 mma.sync (v2:
// A split once cooperatively into smem, B pre-split by prep).
// Block 128x64, 8 warps, K=64.
// ---------------------------------------------------------------------------
#define S3PAD 68

__global__ __launch_bounds__(256) void stage3_kernel(
    const float* __restrict__ out_b,
    float* __restrict__ out)
{
    extern __shared__ float smem3[];
    float* sAh = smem3;                   // [128][S3PAD]
    float* sAl = sAh + 128 * S3PAD;       // [128][S3PAD]
    float* sBh = sAl + 128 * S3PAD;       // [64][S3PAD]
    float* sBl = sBh + 64 * S3PAD;        // [64][S3PAD]

    const int tid = threadIdx.x;
    const int rbase = blockIdx.y * 128;
    const int cbase = blockIdx.x * 64;
    const int warp = tid >> 5;
    const int lane = tid & 31;
    const int wm = warp >> 1;
    const int wn = warp & 1;
    const int g = lane >> 2;
    const int tg = lane & 3;

    for (int idx = tid; idx < 128 * 16; idx += 256) {
        int r = idx >> 4, q = idx & 15;
        float4 v = *(const float4*)(g_states + (size_t)(rbase + r) * NN + 4 * q);
        float vv[4] = {v.x, v.y, v.z, v.w};
        float hh[4], ll[4];
#pragma unroll
        for (int j = 0; j < 4; j++) {
            uint32_t h = tf32_hi(vv[j]);
            hh[j] = __uint_as_float(h);
            ll[j] = __uint_as_float(tf32_hi(vv[j] - __uint_as_float(h)));
        }
        *(float4*)(sAh + r * S3PAD + 4 * q) = make_float4(hh[0], hh[1], hh[2], hh[3]);
        *(float4*)(sAl + r * S3PAD + 4 * q) = make_float4(ll[0], ll[1], ll[2], ll[3]);
    }
    for (int idx = tid; idx < 64 * 16; idx += 256) {
        int c = idx >> 4, q = idx & 15;
        *(float4*)(sBh + c * S3PAD + 4 * q) =
            *(const float4*)(g_owh + (size_t)(cbase + c) * NN + 4 * q);
        *(float4*)(sBl + c * S3PAD + 4 * q) =
            *(const float4*)(g_owl + (size_t)(cbase + c) * NN + 4 * q);
    }
    __syncthreads();

    float4 acc[2][4];
#pragma unroll
    for (int i = 0; i < 2; i++)
#pragma unroll
        for (int j = 0; j < 4; j++) acc[i][j] = make_float4(0.f, 0.f, 0.f, 0.f);

#pragma unroll
    for (int k0 = 0; k0 < 64; k0 += 8) {
        uint32_t ahi[2][4], alo[2][4];
#pragma unroll
        for (int mf = 0; mf < 2; mf++) {
            int r0 = wm * 32 + mf * 16 + g;
            ahi[mf][0] = __float_as_uint(sAh[r0 * S3PAD + k0 + tg]);
            ahi[mf][1] = __float_as_uint(sAh[(r0 + 8) * S3PAD + k0 + tg]);
            ahi[mf][2] = __float_as_uint(sAh[r0 * S3PAD + k0 + tg + 4]);
            ahi[mf][3] = __float_as_uint(sAh[(r0 + 8) * S3PAD + k0 + tg + 4]);
            alo[mf][0] = __float_as_uint(sAl[r0 * S3PAD + k0 + tg]);
            alo[mf][1] = __float_as_uint(sAl[(r0 + 8) * S3PAD + k0 + tg]);
            alo[mf][2] = __float_as_uint(sAl[r0 * S3PAD + k0 + tg + 4]);
            alo[mf][3] = __float_as_uint(sAl[(r0 + 8) * S3PAD + k0 + tg + 4]);
        }
        uint32_t bhi[4][2], blo[4][2];
#pragma unroll
        for (int nf = 0; nf < 4; nf++) {
            int c0 = wn * 32 + nf * 8 + g;
            bhi[nf][0] = __float_as_uint(sBh[c0 * S3PAD + k0 + tg]);
            bhi[nf][1] = __float_as_uint(sBh[c0 * S3PAD + k0 + tg + 4]);
            blo[nf][0] = __float_as_uint(sBl[c0 * S3PAD + k0 + tg]);
            blo[nf][1] = __float_as_uint(sBl[c0 * S3PAD + k0 + tg + 4]);
        }
#pragma unroll
        for (int mf = 0; mf < 2; mf++) {
#pragma unroll
            for (int nf = 0; nf < 4; nf++) {
                MMA3(acc[mf][nf], ahi[mf], alo[mf], bhi[nf], blo[nf]);
            }
        }
    }

#pragma unroll
    for (int nf = 0; nf < 4; nf++) {
        int c = cbase + wn * 32 + nf * 8 + 2 * tg;
        float b0 = out_b[c], b1 = out_b[c + 1];
#pragma unroll
        for (int mf = 0; mf < 2; mf++) {
            int r0 = rbase + wm * 32 + mf * 16 + g;
            float4 v = acc[mf][nf];
            *(float2*)(out + (size_t)r0 * DD + c) = make_float2(v.x + b0, v.y + b1);
            *(float2*)(out + (size_t)(r0 + 8) * DD + c) = make_float2(v.z + b0, v.w + b1);
        }
    }
}

// ---------------------------------------------------------------------------
extern "C" void kernel_launch(void* const* d_in, const int* in_sizes, int n_in,
                              void* d_out, int out_size)
{
    const float* x      = (const float*)d_in[0];
    const float* conv_w = (const float*)d_in[1];
    const float* in_w   = (const float*)d_in[2];
    const float* in_b   = (const float*)d_in[3];
    const float* dt_w   = (const float*)d_in[4];
    const float* dt_b   = (const float*)d_in[5];
    const float* tr_w   = (const float*)d_in[6];
    const float* out_w  = (const float*)d_in[7];
    const float* out_b  = (const float*)d_in[8];
    float* out = (float*)d_out;

    const int s1_smem = (64 * XP + 32 * 80 + 32 * 4) * sizeof(float);  // 78336 B
    cudaFuncSetAttribute(stage1a_kernel,
                         cudaFuncAttributeMaxDynamicSharedMemorySize, s1_smem);
    const int s3_smem = (2 * 128 + 2 * 64) * S3PAD * sizeof(float);    // 104448 B
    cudaFuncSetAttribute(stage3_kernel,
                         cudaFuncAttributeMaxDynamicSharedMemorySize, s3_smem);

    prep_ow_kernel<<<256, 256>>>(out_w);
    stage1a_kernel<<<dim3(4, 64), 256, s1_smem>>>(x, conv_w, in_w, dt_w);
    stage1b_kernel<<<256, 256>>>(in_b, dt_b, tr_w);
    scan_kernel<<<8, 32>>>();
    stage3_kernel<<<dim3(16, 128), 256, s3_smem>>>(out_b, out);
}